// round 3
// baseline (speedup 1.0000x reference)
#include <cuda_runtime.h>
#include <math_constants.h>

#define BDIM 4
#define PDIM 64
#define MROWS 256      // BDIM*PDIM
#define DDIM 768
#define NKEYS 2048
#define RDIM 12
#define TOPK 16

// ---------------- scratch (static device globals; no allocation) ------------
__device__ float g_keys[NKEYS * DDIM];        // normalized keys   (6 MB)
__device__ float g_adjsum[NKEYS * NKEYS];     // sum_r adjacency   (16.8 MB)
__device__ float g_scores[MROWS * NKEYS];     // (2 MB)
__device__ float g_w[MROWS * TOPK];
__device__ int   g_idx[MROWS * TOPK];
__device__ float g_nei[MROWS * NKEYS];        // (2 MB)

// ---------------- kernel 1: row-normalize keys ------------------------------
__global__ __launch_bounds__(256) void k_norm(const float* __restrict__ kp) {
    int n = blockIdx.x;
    const float* row = kp + n * DDIM;
    int tid = threadIdx.x;
    float ssq = 0.f;
    for (int i = tid; i < DDIM; i += 256) {
        float v = row[i];
        ssq = fmaf(v, v, ssq);
    }
    #pragma unroll
    for (int o = 16; o > 0; o >>= 1) ssq += __shfl_xor_sync(0xffffffffu, ssq, o);
    __shared__ float sred[8];
    if ((tid & 31) == 0) sred[tid >> 5] = ssq;
    __syncthreads();
    float total = sred[0] + sred[1] + sred[2] + sred[3] +
                  sred[4] + sred[5] + sred[6] + sred[7];
    float inv = rsqrtf(total + 1e-12f);
    for (int i = tid; i < DDIM; i += 256) g_keys[n * DDIM + i] = row[i] * inv;
}

// ---------------- kernel 2: adj_sum = sum_r adjacency[r] --------------------
__global__ __launch_bounds__(256) void k_adjsum(const float* __restrict__ adj) {
    int i = blockIdx.x * 256 + threadIdx.x;          // float4 index, 1,048,576 total
    const float4* a = (const float4*)adj;
    const int stride = NKEYS * NKEYS / 4;            // 1,048,576
    float4 acc = make_float4(0.f, 0.f, 0.f, 0.f);
    #pragma unroll
    for (int r = 0; r < RDIM; r++) {
        float4 v = a[r * stride + i];
        acc.x += v.x; acc.y += v.y; acc.z += v.z; acc.w += v.w;
    }
    ((float4*)g_adjsum)[i] = acc;
}

// ---------------- kernel 3: scores = positions @ keys^T  (NT GEMM) ----------
// C[m][n] = sum_k A[m*K+k] * B[n*K+k]
__global__ __launch_bounds__(256) void k_gemm_nt(const float* __restrict__ A,
                                                 const float* __restrict__ Bm,
                                                 float* __restrict__ C,
                                                 int Kdim, int Ndim) {
    __shared__ float As[16][64];
    __shared__ float Bs[16][64];
    int tid = threadIdx.x;
    int tm = tid >> 4, tn = tid & 15;
    int row0 = blockIdx.y * 64, col0 = blockIdx.x * 64;
    int lm = tid >> 2;            // 0..63
    int lk = (tid & 3) << 2;      // 0,4,8,12
    const float* Arow = A  + (row0 + lm) * Kdim + lk;
    const float* Brow = Bm + (col0 + lm) * Kdim + lk;
    float acc[4][4] = {};
    for (int k0 = 0; k0 < Kdim; k0 += 16) {
        float4 av = *(const float4*)(Arow + k0);
        float4 bv = *(const float4*)(Brow + k0);
        As[lk + 0][lm] = av.x; As[lk + 1][lm] = av.y;
        As[lk + 2][lm] = av.z; As[lk + 3][lm] = av.w;
        Bs[lk + 0][lm] = bv.x; Bs[lk + 1][lm] = bv.y;
        Bs[lk + 2][lm] = bv.z; Bs[lk + 3][lm] = bv.w;
        __syncthreads();
        #pragma unroll
        for (int kk = 0; kk < 16; kk++) {
            float ra[4], rb[4];
            #pragma unroll
            for (int i = 0; i < 4; i++) ra[i] = As[kk][tm * 4 + i];
            #pragma unroll
            for (int j = 0; j < 4; j++) rb[j] = Bs[kk][tn * 4 + j];
            #pragma unroll
            for (int i = 0; i < 4; i++)
                #pragma unroll
                for (int j = 0; j < 4; j++)
                    acc[i][j] = fmaf(ra[i], rb[j], acc[i][j]);
        }
        __syncthreads();
    }
    #pragma unroll
    for (int i = 0; i < 4; i++) {
        float4 v = make_float4(acc[i][0], acc[i][1], acc[i][2], acc[i][3]);
        *(float4*)&C[(row0 + tm * 4 + i) * Ndim + col0 + tn * 4] = v;
    }
}

// ---------------- kernel 4: per-row top-16 + softmax ------------------------
__global__ __launch_bounds__(256) void k_topk() {
    int row = blockIdx.x;
    int tid = threadIdx.x;
    __shared__ float s[NKEYS];
    __shared__ float rv[256];
    __shared__ int   ri[256];
    __shared__ float vals[TOPK];
    __shared__ int   inds[TOPK];
    for (int j = tid; j < NKEYS; j += 256) s[j] = g_scores[row * NKEYS + j];
    __syncthreads();
    for (int it = 0; it < TOPK; it++) {
        float best = -CUDART_INF_F;
        int bi = NKEYS;
        for (int j = tid; j < NKEYS; j += 256) {
            float v = s[j];
            if (v > best) { best = v; bi = j; }
        }
        rv[tid] = best; ri[tid] = bi;
        __syncthreads();
        for (int off = 128; off > 0; off >>= 1) {
            if (tid < off) {
                float ov = rv[tid + off]; int oi = ri[tid + off];
                if (ov > rv[tid] || (ov == rv[tid] && oi < ri[tid])) {
                    rv[tid] = ov; ri[tid] = oi;
                }
            }
            __syncthreads();
        }
        if (tid == 0) {
            vals[it] = rv[0];
            inds[it] = ri[0];
            s[ri[0]] = -CUDART_INF_F;
        }
        __syncthreads();
    }
    if (tid == 0) {
        float mx = vals[0];        // descending order -> vals[0] is max
        float e[TOPK];
        float sum = 0.f;
        #pragma unroll
        for (int i = 0; i < TOPK; i++) { e[i] = expf(vals[i] - mx); sum += e[i]; }
        float inv = 1.f / sum;
        #pragma unroll
        for (int i = 0; i < TOPK; i++) {
            g_w[row * TOPK + i]   = e[i] * inv;
            g_idx[row * TOPK + i] = inds[i];
        }
    }
}

// ---------------- kernel 5: nei = w-weighted gather of adj_sum rows ---------
__global__ __launch_bounds__(256) void k_nei() {
    int row = blockIdx.x;
    int tid = threadIdx.x;
    __shared__ float sw[TOPK];
    __shared__ int   si[TOPK];
    if (tid < TOPK) { sw[tid] = g_w[row * TOPK + tid]; si[tid] = g_idx[row * TOPK + tid]; }
    __syncthreads();
    int n0 = tid * 8;
    float4 a0 = make_float4(0.f, 0.f, 0.f, 0.f);
    float4 a1 = make_float4(0.f, 0.f, 0.f, 0.f);
    #pragma unroll
    for (int kk = 0; kk < TOPK; kk++) {
        float wv = sw[kk];
        const float4* p = (const float4*)&g_adjsum[si[kk] * NKEYS + n0];
        float4 v0 = p[0], v1 = p[1];
        a0.x = fmaf(wv, v0.x, a0.x); a0.y = fmaf(wv, v0.y, a0.y);
        a0.z = fmaf(wv, v0.z, a0.z); a0.w = fmaf(wv, v0.w, a0.w);
        a1.x = fmaf(wv, v1.x, a1.x); a1.y = fmaf(wv, v1.y, a1.y);
        a1.z = fmaf(wv, v1.z, a1.z); a1.w = fmaf(wv, v1.w, a1.w);
    }
    float4* o = (float4*)&g_nei[row * NKEYS + n0];
    o[0] = a0; o[1] = a1;
}

// ---------------- kernel 6: zero d_out --------------------------------------
__global__ __launch_bounds__(256) void k_zero(float* __restrict__ C) {
    C[blockIdx.x * 256 + threadIdx.x] = 0.f;
}

// ---------------- kernel 7: out = nei @ keys  (NN GEMM, split-K + atomics) --
// A [M][K] (K contig), B [K][N] (N contig), C accumulated atomically.
__global__ __launch_bounds__(256) void k_gemm_nn_splitk(const float* __restrict__ A,
                                                        const float* __restrict__ Bm,
                                                        float* __restrict__ C,
                                                        int Kdim, int Ndim, int KS) {
    __shared__ float As[16][64];
    __shared__ float Bs[16][64];
    int tid = threadIdx.x;
    int tm = tid >> 4, tn = tid & 15;
    int row0 = blockIdx.y * 64, col0 = blockIdx.x * 64;
    int kbase = blockIdx.z * KS;
    int lm  = tid >> 2;           // A tile: 0..63
    int lk  = (tid & 3) << 2;     // 0,4,8,12
    int lkb = tid >> 4;           // B tile: row 0..15
    int lnb = (tid & 15) << 2;    // col 0,4,..,60
    float acc[4][4] = {};
    for (int k0 = kbase; k0 < kbase + KS; k0 += 16) {
        float4 av = *(const float4*)&A[(row0 + lm) * Kdim + k0 + lk];
        As[lk + 0][lm] = av.x; As[lk + 1][lm] = av.y;
        As[lk + 2][lm] = av.z; As[lk + 3][lm] = av.w;
        float4 bv = *(const float4*)&Bm[(k0 + lkb) * Ndim + col0 + lnb];
        *(float4*)&Bs[lkb][lnb] = bv;
        __syncthreads();
        #pragma unroll
        for (int kk = 0; kk < 16; kk++) {
            float ra[4], rb[4];
            #pragma unroll
            for (int i = 0; i < 4; i++) ra[i] = As[kk][tm * 4 + i];
            #pragma unroll
            for (int j = 0; j < 4; j++) rb[j] = Bs[kk][tn * 4 + j];
            #pragma unroll
            for (int i = 0; i < 4; i++)
                #pragma unroll
                for (int j = 0; j < 4; j++)
                    acc[i][j] = fmaf(ra[i], rb[j], acc[i][j]);
        }
        __syncthreads();
    }
    #pragma unroll
    for (int i = 0; i < 4; i++)
        #pragma unroll
        for (int j = 0; j < 4; j++)
            atomicAdd(&C[(row0 + tm * 4 + i) * Ndim + col0 + tn * 4 + j], acc[i][j]);
}

// ---------------- launch ----------------------------------------------------
extern "C" void kernel_launch(void* const* d_in, const int* in_sizes, int n_in,
                              void* d_out, int out_size) {
    const float* positions  = (const float*)d_in[0];   // [4,64,768]
    const float* keys_param = (const float*)d_in[1];   // [2048,768]
    const float* adjacency  = (const float*)d_in[2];   // [12,2048,2048]
    float* out = (float*)d_out;                        // [4,64,768]

    float *p_keys, *p_adjsum, *p_scores, *p_nei;
    cudaGetSymbolAddress((void**)&p_keys,   g_keys);
    cudaGetSymbolAddress((void**)&p_adjsum, g_adjsum);
    cudaGetSymbolAddress((void**)&p_scores, g_scores);
    cudaGetSymbolAddress((void**)&p_nei,    g_nei);

    // 1. normalize keys
    k_norm<<<NKEYS, 256>>>(keys_param);
    // 2. adjacency reduction over R (dominant HBM pass)
    k_adjsum<<<NKEYS * NKEYS / 4 / 256, 256>>>(adjacency);
    // 3. scores = positions @ keys^T  : M=256, N=2048, K=768
    {
        dim3 grid(NKEYS / 64, MROWS / 64);
        k_gemm_nt<<<grid, 256>>>(positions, p_keys, p_scores, DDIM, NKEYS);
    }
    // 4. top-16 + softmax per row
    k_topk<<<MROWS, 256>>>();
    // 5. nei gather (adj_sum rows live in L2)
    k_nei<<<MROWS, 256>>>();
    // 6+7. out = nei @ keys : M=256, N=768, K=2048, split-K=4
    k_zero<<<MROWS * DDIM / 256, 256>>>(out);
    {
        dim3 grid(DDIM / 64, MROWS / 64, 4);
        k_gemm_nn_splitk<<<grid, 256>>>(p_nei, p_keys, out, NKEYS, DDIM, NKEYS / 4);
    }
}

// round 4
// speedup vs baseline: 1.2140x; 1.2140x over previous
#include <cuda_runtime.h>
#include <math_constants.h>

#define BDIM 4
#define PDIM 64
#define MROWS 256      // BDIM*PDIM
#define DDIM 768
#define NKEYS 2048
#define RDIM 12
#define TOPK 16

// ---------------- scratch (static device globals; no allocation) ------------
__device__ float g_keys[NKEYS * DDIM];        // normalized keys   (6 MB)
__device__ float g_adjsum[NKEYS * NKEYS];     // sum_r adjacency   (16.8 MB)
__device__ float g_scoresA[MROWS * NKEYS];    // split-K partial 0 (2 MB)
__device__ float g_scoresB[MROWS * NKEYS];    // split-K partial 1 (2 MB)
__device__ float g_w[MROWS * TOPK];
__device__ int   g_idx[MROWS * TOPK];
__device__ int   g_used[NKEYS];               // rows referenced by any topk
__device__ float g_nei[MROWS * NKEYS];        // (2 MB)

// ---------------- kernel 1: row-normalize keys ------------------------------
__global__ __launch_bounds__(256) void k_norm(const float* __restrict__ kp) {
    int n = blockIdx.x;
    const float* row = kp + n * DDIM;
    int tid = threadIdx.x;
    float ssq = 0.f;
    for (int i = tid; i < DDIM; i += 256) {
        float v = row[i];
        ssq = fmaf(v, v, ssq);
    }
    #pragma unroll
    for (int o = 16; o > 0; o >>= 1) ssq += __shfl_xor_sync(0xffffffffu, ssq, o);
    __shared__ float sred[8];
    if ((tid & 31) == 0) sred[tid >> 5] = ssq;
    __syncthreads();
    float total = sred[0] + sred[1] + sred[2] + sred[3] +
                  sred[4] + sred[5] + sred[6] + sred[7];
    float inv = rsqrtf(total + 1e-12f);
    for (int i = tid; i < DDIM; i += 256) g_keys[n * DDIM + i] = row[i] * inv;
}

// ---------------- kernel: zero the used-row mask ----------------------------
__global__ __launch_bounds__(256) void k_zero_used() {
    g_used[blockIdx.x * 256 + threadIdx.x] = 0;
}

// ---------------- kernel 2: adj_sum = sum_r adjacency[r]  (used rows only) --
// 2 blocks per row; each thread one float4.
__global__ __launch_bounds__(256) void k_adjsum(const float* __restrict__ adj) {
    int row = blockIdx.x >> 1;
    if (!g_used[row]) return;
    int i = row * (NKEYS / 4) + (blockIdx.x & 1) * 256 + threadIdx.x;
    const float4* a = (const float4*)adj;
    const int stride = NKEYS * NKEYS / 4;
    float4 acc = make_float4(0.f, 0.f, 0.f, 0.f);
    #pragma unroll
    for (int r = 0; r < RDIM; r++) {
        float4 v = a[r * stride + i];
        acc.x += v.x; acc.y += v.y; acc.z += v.z; acc.w += v.w;
    }
    ((float4*)g_adjsum)[i] = acc;
}

// ---------------- kernel 3: scores = positions @ keys^T  (NT GEMM, split-K=2)
// C[m][n] = sum_k A[m*K+k] * B[n*K+k]; blockIdx.z selects K half + out buffer.
__global__ __launch_bounds__(256) void k_gemm_nt(const float* __restrict__ A,
                                                 const float* __restrict__ Bm,
                                                 float* __restrict__ C0,
                                                 float* __restrict__ C1,
                                                 int Kdim, int Ndim) {
    __shared__ float As[16][64];
    __shared__ float Bs[16][64];
    int tid = threadIdx.x;
    int tm = tid >> 4, tn = tid & 15;
    int row0 = blockIdx.y * 64, col0 = blockIdx.x * 64;
    int kbase = blockIdx.z * (Kdim / 2);
    float* C = blockIdx.z ? C1 : C0;
    int lm = tid >> 2;            // 0..63
    int lk = (tid & 3) << 2;      // 0,4,8,12
    const float* Arow = A  + (row0 + lm) * Kdim + lk;
    const float* Brow = Bm + (col0 + lm) * Kdim + lk;
    float acc[4][4] = {};
    for (int k0 = kbase; k0 < kbase + Kdim / 2; k0 += 16) {
        float4 av = *(const float4*)(Arow + k0);
        float4 bv = *(const float4*)(Brow + k0);
        As[lk + 0][lm] = av.x; As[lk + 1][lm] = av.y;
        As[lk + 2][lm] = av.z; As[lk + 3][lm] = av.w;
        Bs[lk + 0][lm] = bv.x; Bs[lk + 1][lm] = bv.y;
        Bs[lk + 2][lm] = bv.z; Bs[lk + 3][lm] = bv.w;
        __syncthreads();
        #pragma unroll
        for (int kk = 0; kk < 16; kk++) {
            float ra[4], rb[4];
            #pragma unroll
            for (int i = 0; i < 4; i++) ra[i] = As[kk][tm * 4 + i];
            #pragma unroll
            for (int j = 0; j < 4; j++) rb[j] = Bs[kk][tn * 4 + j];
            #pragma unroll
            for (int i = 0; i < 4; i++)
                #pragma unroll
                for (int j = 0; j < 4; j++)
                    acc[i][j] = fmaf(ra[i], rb[j], acc[i][j]);
        }
        __syncthreads();
    }
    #pragma unroll
    for (int i = 0; i < 4; i++) {
        float4 v = make_float4(acc[i][0], acc[i][1], acc[i][2], acc[i][3]);
        *(float4*)&C[(row0 + tm * 4 + i) * Ndim + col0 + tn * 4] = v;
    }
}

// ---------------- kernel 4: per-row top-16 + softmax (register-resident) ----
// Pack (value, index) into one orderable u64: larger value wins, ties -> lower
// index wins (via ~idx in low bits).
__device__ __forceinline__ unsigned long long tk_pack(float v, int idx) {
    unsigned u = __float_as_uint(v);
    u = (u & 0x80000000u) ? ~u : (u | 0x80000000u);
    return ((unsigned long long)u << 32) | (unsigned)(~idx);
}

__global__ __launch_bounds__(256) void k_topk() {
    int row = blockIdx.x;
    int tid = threadIdx.x;
    int wid = tid >> 5, lane = tid & 31;
    __shared__ unsigned long long sh[8];
    __shared__ float svals[TOPK];
    __shared__ int   sidx[TOPK];

    // 8 scores per thread, strided for coalescing; sum the two split-K halves.
    float v[8];
    #pragma unroll
    for (int j = 0; j < 8; j++) {
        int n = tid + 256 * j;
        v[j] = g_scoresA[row * NKEYS + n] + g_scoresB[row * NKEYS + n];
    }

    for (int it = 0; it < TOPK; it++) {
        // local argmax over 8 registers
        unsigned long long best = tk_pack(v[0], tid);
        #pragma unroll
        for (int j = 1; j < 8; j++) {
            unsigned long long c = tk_pack(v[j], tid + 256 * j);
            if (c > best) best = c;
        }
        // warp argmax
        #pragma unroll
        for (int o = 16; o > 0; o >>= 1) {
            unsigned long long c = __shfl_xor_sync(0xffffffffu, best, o);
            if (c > best) best = c;
        }
        if (lane == 0) sh[wid] = best;
        __syncthreads();
        if (tid < 32) {
            unsigned long long b = (tid < 8) ? sh[tid] : 0ull;
            #pragma unroll
            for (int o = 4; o > 0; o >>= 1) {
                unsigned long long c = __shfl_xor_sync(0xffffffffu, b, o);
                if (c > b) b = c;
            }
            if (tid == 0) sh[0] = b;
        }
        __syncthreads();
        unsigned long long win = sh[0];
        int widx = ~(unsigned)(win & 0xffffffffull);
        // invalidate winner in its owner's registers
        if ((widx & 255) == tid) v[widx >> 8] = -CUDART_INF_F;
        if (tid == 0) {
            unsigned u = (unsigned)(win >> 32);
            unsigned vb = (u & 0x80000000u) ? (u & 0x7fffffffu) : ~u;
            svals[it] = __uint_as_float(vb);
            sidx[it]  = widx;
        }
        __syncthreads();
    }
    if (tid == 0) {
        float mx = svals[0];              // descending -> svals[0] is max
        float e[TOPK], sum = 0.f;
        #pragma unroll
        for (int i = 0; i < TOPK; i++) { e[i] = expf(svals[i] - mx); sum += e[i]; }
        float inv = 1.f / sum;
        #pragma unroll
        for (int i = 0; i < TOPK; i++) {
            g_w[row * TOPK + i]   = e[i] * inv;
            g_idx[row * TOPK + i] = sidx[i];
            g_used[sidx[i]] = 1;          // benign races: all write 1
        }
    }
}

// ---------------- kernel 5: nei = w-weighted gather of adj_sum rows ---------
// grid (MROWS, 2): each block covers half a row; one float4 per thread.
__global__ __launch_bounds__(256) void k_nei() {
    int row = blockIdx.x;
    int tid = threadIdx.x;
    __shared__ float sw[TOPK];
    __shared__ int   si[TOPK];
    if (tid < TOPK) { sw[tid] = g_w[row * TOPK + tid]; si[tid] = g_idx[row * TOPK + tid]; }
    __syncthreads();
    int n0 = blockIdx.y * (NKEYS / 2) + tid * 4;
    float4 a0 = make_float4(0.f, 0.f, 0.f, 0.f);
    #pragma unroll
    for (int kk = 0; kk < TOPK; kk++) {
        float wv = sw[kk];
        float4 v0 = *(const float4*)&g_adjsum[si[kk] * NKEYS + n0];
        a0.x = fmaf(wv, v0.x, a0.x); a0.y = fmaf(wv, v0.y, a0.y);
        a0.z = fmaf(wv, v0.z, a0.z); a0.w = fmaf(wv, v0.w, a0.w);
    }
    *(float4*)&g_nei[row * NKEYS + n0] = a0;
}

// ---------------- kernel 6: zero d_out --------------------------------------
__global__ __launch_bounds__(256) void k_zero(float* __restrict__ C) {
    C[blockIdx.x * 256 + threadIdx.x] = 0.f;
}

// ---------------- kernel 7: out = nei @ keys  (NN GEMM, split-K + atomics) --
__global__ __launch_bounds__(256) void k_gemm_nn_splitk(const float* __restrict__ A,
                                                        const float* __restrict__ Bm,
                                                        float* __restrict__ C,
                                                        int Kdim, int Ndim, int KS) {
    __shared__ float As[16][64];
    __shared__ float Bs[16][64];
    int tid = threadIdx.x;
    int tm = tid >> 4, tn = tid & 15;
    int row0 = blockIdx.y * 64, col0 = blockIdx.x * 64;
    int kbase = blockIdx.z * KS;
    int lm  = tid >> 2;           // A tile: 0..63
    int lk  = (tid & 3) << 2;     // 0,4,8,12
    int lkb = tid >> 4;           // B tile: row 0..15
    int lnb = (tid & 15) << 2;    // col 0,4,..,60
    float acc[4][4] = {};
    for (int k0 = kbase; k0 < kbase + KS; k0 += 16) {
        float4 av = *(const float4*)&A[(row0 + lm) * Kdim + k0 + lk];
        As[lk + 0][lm] = av.x; As[lk + 1][lm] = av.y;
        As[lk + 2][lm] = av.z; As[lk + 3][lm] = av.w;
        float4 bv = *(const float4*)&Bm[(k0 + lkb) * Ndim + col0 + lnb];
        *(float4*)&Bs[lkb][lnb] = bv;
        __syncthreads();
        #pragma unroll
        for (int kk = 0; kk < 16; kk++) {
            float ra[4], rb[4];
            #pragma unroll
            for (int i = 0; i < 4; i++) ra[i] = As[kk][tm * 4 + i];
            #pragma unroll
            for (int j = 0; j < 4; j++) rb[j] = Bs[kk][tn * 4 + j];
            #pragma unroll
            for (int i = 0; i < 4; i++)
                #pragma unroll
                for (int j = 0; j < 4; j++)
                    acc[i][j] = fmaf(ra[i], rb[j], acc[i][j]);
        }
        __syncthreads();
    }
    #pragma unroll
    for (int i = 0; i < 4; i++)
        #pragma unroll
        for (int j = 0; j < 4; j++)
            atomicAdd(&C[(row0 + tm * 4 + i) * Ndim + col0 + tn * 4 + j], acc[i][j]);
}

// ---------------- launch ----------------------------------------------------
extern "C" void kernel_launch(void* const* d_in, const int* in_sizes, int n_in,
                              void* d_out, int out_size) {
    const float* positions  = (const float*)d_in[0];   // [4,64,768]
    const float* keys_param = (const float*)d_in[1];   // [2048,768]
    const float* adjacency  = (const float*)d_in[2];   // [12,2048,2048]
    float* out = (float*)d_out;                        // [4,64,768]

    float *p_keys, *p_scoresA, *p_scoresB, *p_nei;
    cudaGetSymbolAddress((void**)&p_keys,    g_keys);
    cudaGetSymbolAddress((void**)&p_scoresA, g_scoresA);
    cudaGetSymbolAddress((void**)&p_scoresB, g_scoresB);
    cudaGetSymbolAddress((void**)&p_nei,     g_nei);

    // 1. normalize keys; reset used-mask
    k_norm<<<NKEYS, 256>>>(keys_param);
    k_zero_used<<<NKEYS / 256, 256>>>();
    // 2. scores = positions @ keys^T : M=256, N=2048, K=768, split-K=2
    {
        dim3 grid(NKEYS / 64, MROWS / 64, 2);
        k_gemm_nt<<<grid, 256>>>(positions, p_keys, p_scoresA, p_scoresB,
                                 DDIM, NKEYS);
    }
    // 3. top-16 + softmax per row (also marks used adjacency rows)
    k_topk<<<MROWS, 256>>>();
    // 4. adjacency reduction over R, only rows referenced by some topk
    k_adjsum<<<NKEYS * 2, 256>>>(adjacency);
    // 5. nei gather (adj_sum rows live in L2)
    {
        dim3 grid(MROWS, 2);
        k_nei<<<grid, 256>>>();
    }
    // 6+7. out = nei @ keys : M=256, N=768, K=2048, split-K=4
    k_zero<<<MROWS * DDIM / 256, 256>>>(out);
    {
        dim3 grid(DDIM / 64, MROWS / 64, 4);
        k_gemm_nn_splitk<<<grid, 256>>>(p_nei, p_keys, out, NKEYS, DDIM, NKEYS / 4);
    }
}

// round 6
// speedup vs baseline: 1.8815x; 1.5499x over previous
#include <cuda_runtime.h>
#include <cuda_bf16.h>
#include <math_constants.h>
#include <stdint.h>

#define MROWS 256      // 4*64 query rows
#define DDIM 768
#define NKEYS 2048
#define RDIM 12
#define TOPK 16

// ---------------- scratch (static device globals; no allocation) ------------
__device__ __align__(16) __nv_bfloat16 g_keysh [NKEYS * DDIM];
__device__ __align__(16) __nv_bfloat16 g_keysl [NKEYS * DDIM];
__device__ __align__(16) __nv_bfloat16 g_keysTh[DDIM * NKEYS];
__device__ __align__(16) __nv_bfloat16 g_keysTl[DDIM * NKEYS];
__device__ __align__(16) __nv_bfloat16 g_posh  [MROWS * DDIM];
__device__ __align__(16) __nv_bfloat16 g_posl  [MROWS * DDIM];
__device__ __align__(16) __nv_bfloat16 g_neih  [MROWS * NKEYS];
__device__ __align__(16) __nv_bfloat16 g_neil  [MROWS * NKEYS];
__device__ __align__(16) float g_adjsum [NKEYS * NKEYS];       // 16.8 MB
__device__ __align__(16) float g_scores4[4 * MROWS * NKEYS];   // split-K buffers
__device__ __align__(16) float g_outp   [8 * MROWS * DDIM];    // split-K buffers
__device__ float g_w[MROWS * TOPK];
__device__ int   g_idx[MROWS * TOPK];
__device__ int   g_used[NKEYS];

// ---------------- generic PTX helpers (no sm_103a-only features) ------------
__device__ __forceinline__ uint32_t smem_u32(const void* p) {
    uint32_t a;
    asm("{ .reg .u64 t; cvta.to.shared.u64 t, %1; cvt.u32.u64 %0, t; }"
        : "=r"(a) : "l"(p));
    return a;
}

#define SWZ128(off) ((off) ^ (((off) >> 3) & 0x70))

__device__ __forceinline__ void cpasync16(uint32_t saddr, const void* g) {
    asm volatile("cp.async.cg.shared.global [%0], [%1], 16;"
                 :: "r"(saddr), "l"(g) : "memory");
}
#define CP_COMMIT() asm volatile("cp.async.commit_group;" ::: "memory")
#define CP_WAIT(n)  asm volatile("cp.async.wait_group %0;" :: "n"(n) : "memory")

__device__ __forceinline__ void ldm_x4(uint32_t* r, uint32_t addr) {
    asm volatile("ldmatrix.sync.aligned.m8n8.x4.shared.b16 {%0,%1,%2,%3}, [%4];"
                 : "=r"(r[0]), "=r"(r[1]), "=r"(r[2]), "=r"(r[3]) : "r"(addr));
}
__device__ __forceinline__ void ldm_x2(uint32_t* r, uint32_t addr) {
    asm volatile("ldmatrix.sync.aligned.m8n8.x2.shared.b16 {%0,%1}, [%2];"
                 : "=r"(r[0]), "=r"(r[1]) : "r"(addr));
}

__device__ __forceinline__ void mma16816(float* c, const uint32_t* a, const uint32_t* b) {
    asm volatile(
        "mma.sync.aligned.m16n8k16.row.col.f32.bf16.bf16.f32 "
        "{%0,%1,%2,%3}, {%4,%5,%6,%7}, {%8,%9}, {%0,%1,%2,%3};"
        : "+f"(c[0]), "+f"(c[1]), "+f"(c[2]), "+f"(c[3])
        : "r"(a[0]), "r"(a[1]), "r"(a[2]), "r"(a[3]), "r"(b[0]), "r"(b[1]));
}

// bf16 hi/lo packing helpers
__device__ __forceinline__ unsigned pack_hi2(float a, float b) {
    return (unsigned)__bfloat16_as_ushort(__float2bfloat16(a)) |
           ((unsigned)__bfloat16_as_ushort(__float2bfloat16(b)) << 16);
}
__device__ __forceinline__ unsigned pack_lo2(float a, float b) {
    float ra = a - __bfloat162float(__float2bfloat16(a));
    float rb = b - __bfloat162float(__float2bfloat16(b));
    return (unsigned)__bfloat16_as_ushort(__float2bfloat16(ra)) |
           ((unsigned)__bfloat16_as_ushort(__float2bfloat16(rb)) << 16);
}

// ---------------- kernel 1: normalize keys -> hi/lo planes; zero used-mask --
__global__ __launch_bounds__(256) void k_norm(const float* __restrict__ kp) {
    int n = blockIdx.x;
    int tid = threadIdx.x;
    const float* row = kp + n * DDIM;
    float ssq = 0.f;
    for (int i = tid; i < DDIM; i += 256) { float v = row[i]; ssq = fmaf(v, v, ssq); }
    #pragma unroll
    for (int o = 16; o > 0; o >>= 1) ssq += __shfl_xor_sync(0xffffffffu, ssq, o);
    __shared__ float sr[8];
    if ((tid & 31) == 0) sr[tid >> 5] = ssq;
    __syncthreads();
    float tot = sr[0] + sr[1] + sr[2] + sr[3] + sr[4] + sr[5] + sr[6] + sr[7];
    float inv = rsqrtf(tot + 1e-12f);
    for (int i = tid; i < DDIM; i += 256) {
        float v = row[i] * inv;
        __nv_bfloat16 h = __float2bfloat16(v);
        g_keysh[n * DDIM + i] = h;
        g_keysl[n * DDIM + i] = __float2bfloat16(v - __bfloat162float(h));
    }
    if (tid == 0) g_used[n] = 0;
}

// ---------------- kernel 2: positions -> hi/lo planes -----------------------
__global__ __launch_bounds__(256) void k_prep(const float* __restrict__ pos) {
    int i4 = blockIdx.x * 256 + threadIdx.x;             // < 49152
    float4 v = ((const float4*)pos)[i4];
    uint2 H, L;
    H.x = pack_hi2(v.x, v.y); H.y = pack_hi2(v.z, v.w);
    L.x = pack_lo2(v.x, v.y); L.y = pack_lo2(v.z, v.w);
    ((uint2*)g_posh)[i4] = H;
    ((uint2*)g_posl)[i4] = L;
}

// ---------------- kernel 3: transpose keys planes -> keysT ------------------
__global__ __launch_bounds__(256) void k_transpose() {
    __shared__ __nv_bfloat16 th[32][33], tl[32][33];
    int tx = threadIdx.x & 31, ty = threadIdx.x >> 5;    // 32 x 8
    int d0 = blockIdx.x * 32, n0 = blockIdx.y * 32;
    #pragma unroll
    for (int i = 0; i < 32; i += 8) {
        int n = n0 + ty + i, d = d0 + tx;
        th[ty + i][tx] = g_keysh[n * DDIM + d];
        tl[ty + i][tx] = g_keysl[n * DDIM + d];
    }
    __syncthreads();
    #pragma unroll
    for (int i = 0; i < 32; i += 8) {
        int d = d0 + ty + i, n = n0 + tx;
        g_keysTh[d * NKEYS + n] = th[tx][ty + i];
        g_keysTl[d * NKEYS + n] = tl[tx][ty + i];
    }
}

// ---------------- kernel 4: HMMA bf16-split NT GEMM -------------------------
// C_split[z](row0:+128, col0:+128) = A @ B^T over K-split slice.
// A[hi/lo]: [M][K] bf16 K-contig; B[hi/lo]: [N][K] bf16 K-contig.
// Grid (N/128, M/128, nsplit); Kper multiple of 64; 256 threads (8 warps 2x4).
// Dynamic smem: 2 stages x 4 tiles x (128x64 bf16, SW128) = 131072 B.
#define TILE_B   16384
#define STAGE_B  65536
__global__ __launch_bounds__(256)
void k_gemm(const __nv_bfloat16* __restrict__ Ah, const __nv_bfloat16* __restrict__ Al,
            const __nv_bfloat16* __restrict__ Bh, const __nv_bfloat16* __restrict__ Bl,
            float* __restrict__ Cbase, int K, int Kper, int ldc) {
    extern __shared__ char smem[];
    const int tid = threadIdx.x, lane = tid & 31, wid = tid >> 5;
    const int warpM = wid >> 2, warpN = wid & 3;          // 2 x 4 warp grid
    const int col0 = blockIdx.x * 128, row0 = blockIdx.y * 128;
    const int kbeg = blockIdx.z * Kper;
    float* C = Cbase + (size_t)blockIdx.z * MROWS * ldc;
    const uint32_t sb0 = smem_u32(smem);

    float acc[4][4][4] = {};

    // stage loader: 4 tiles (Ah, Al, Bh, Bl), each 128 rows x 128 B, SW128
    auto issue = [&](int stage, int k0) {
        uint32_t st = sb0 + stage * STAGE_B;
        #pragma unroll
        for (int t = 0; t < 4; t++) {
            const __nv_bfloat16* src = (t == 0) ? Ah : (t == 1) ? Al
                                      : (t == 2) ? Bh : Bl;
            int rbase = (t < 2) ? row0 : col0;
            #pragma unroll
            for (int j = 0; j < 4; j++) {
                int c = tid + 256 * j;                    // 0..1023
                int r = c >> 3, seg = c & 7;
                uint32_t so = st + t * TILE_B + SWZ128((uint32_t)(r * 128 + seg * 16));
                cpasync16(so, src + (size_t)(rbase + r) * K + k0 + seg * 8);
            }
        }
    };

    const int nch = Kper >> 6;
    issue(0, kbeg);
    CP_COMMIT();

    const int rA = lane & 15, selA = lane >> 4;
    const int rB = lane & 7,  selB = (lane >> 3) & 1;

    for (int c = 0; c < nch; c++) {
        if (c + 1 < nch) { issue((c + 1) & 1, kbeg + (c + 1) * 64); CP_COMMIT(); CP_WAIT(1); }
        else             { CP_WAIT(0); }
        __syncthreads();
        uint32_t st = sb0 + (c & 1) * STAGE_B;
        uint32_t tAh = st, tAl = st + TILE_B, tBh = st + 2 * TILE_B, tBl = st + 3 * TILE_B;
        #pragma unroll
        for (int ks = 0; ks < 4; ks++) {
            uint32_t ah[4][4], al[4][4], bh[4][2], bl[4][2];
            #pragma unroll
            for (int tm = 0; tm < 4; tm++) {
                uint32_t off = SWZ128((uint32_t)((warpM * 64 + tm * 16 + rA) * 128 +
                                                 (ks * 16 + selA * 8) * 2));
                ldm_x4(ah[tm], tAh + off);
                ldm_x4(al[tm], tAl + off);
            }
            #pragma unroll
            for (int tn = 0; tn < 4; tn++) {
                uint32_t off = SWZ128((uint32_t)((warpN * 32 + tn * 8 + rB) * 128 +
                                                 (ks * 16 + selB * 8) * 2));
                ldm_x2(bh[tn], tBh + off);
                ldm_x2(bl[tn], tBl + off);
            }
            #pragma unroll
            for (int tm = 0; tm < 4; tm++)
                #pragma unroll
                for (int tn = 0; tn < 4; tn++) {
                    mma16816(acc[tm][tn], ah[tm], bh[tn]);
                    mma16816(acc[tm][tn], ah[tm], bl[tn]);
                    mma16816(acc[tm][tn], al[tm], bh[tn]);
                }
        }
        __syncthreads();
    }

    // epilogue: fragment rows/cols -> C
    #pragma unroll
    for (int tm = 0; tm < 4; tm++) {
        int r0 = row0 + warpM * 64 + tm * 16 + (lane >> 2);
        #pragma unroll
        for (int tn = 0; tn < 4; tn++) {
            int col = col0 + warpN * 32 + tn * 8 + (lane & 3) * 2;
            *(float2*)&C[(size_t)r0 * ldc + col] =
                make_float2(acc[tm][tn][0], acc[tm][tn][1]);
            *(float2*)&C[(size_t)(r0 + 8) * ldc + col] =
                make_float2(acc[tm][tn][2], acc[tm][tn][3]);
        }
    }
}

// ---------------- kernel 5: top-16 + softmax (two-level warp argmax) --------
__device__ __forceinline__ unsigned long long tk_pack(float v, int idx) {
    unsigned u = __float_as_uint(v);
    u = (u & 0x80000000u) ? ~u : (u | 0x80000000u);
    return ((unsigned long long)u << 32) | (unsigned)(~idx);
}

__global__ __launch_bounds__(256) void k_topk() {
    int row = blockIdx.x;
    int tid = threadIdx.x, wid = tid >> 5, lane = tid & 31;
    __shared__ unsigned long long cand[8 * TOPK];
    __shared__ float svals[TOPK];
    __shared__ int   sidx[TOPK];

    // warp w owns n in [w*256, w*256+256); lane-coalesced; sum 4 split buffers
    float v[8];
    #pragma unroll
    for (int j = 0; j < 8; j++) {
        int n = wid * 256 + lane + 32 * j;
        int o = row * NKEYS + n;
        v[j] = g_scores4[o] + g_scores4[MROWS * NKEYS + o] +
               g_scores4[2 * MROWS * NKEYS + o] + g_scores4[3 * MROWS * NKEYS + o];
    }
    // per-warp top-16 (no barriers)
    for (int it = 0; it < TOPK; it++) {
        unsigned long long best = tk_pack(v[0], wid * 256 + lane);
        #pragma unroll
        for (int j = 1; j < 8; j++) {
            unsigned long long c = tk_pack(v[j], wid * 256 + lane + 32 * j);
            if (c > best) best = c;
        }
        #pragma unroll
        for (int o = 16; o > 0; o >>= 1) {
            unsigned long long c = __shfl_xor_sync(0xffffffffu, best, o);
            if (c > best) best = c;
        }
        if (lane == 0) cand[wid * TOPK + it] = best;
        int local = (~(unsigned)(best & 0xffffffffull)) - wid * 256;
        if ((local & 31) == lane) v[local >> 5] = __int_as_float(0xff800000);
    }
    __syncthreads();
    // warp 0 merges the 128 candidates
    if (wid == 0) {
        unsigned long long c[4];
        #pragma unroll
        for (int j = 0; j < 4; j++) c[j] = cand[lane + 32 * j];
        for (int it = 0; it < TOPK; it++) {
            unsigned long long best = c[0];
            #pragma unroll
            for (int j = 1; j < 4; j++) if (c[j] > best) best = c[j];
            #pragma unroll
            for (int o = 16; o > 0; o >>= 1) {
                unsigned long long t = __shfl_xor_sync(0xffffffffu, best, o);
                if (t > best) best = t;
            }
            #pragma unroll
            for (int j = 0; j < 4; j++) if (c[j] == best) c[j] = 0ull;
            if (lane == 0) {
                unsigned u = (unsigned)(best >> 32);
                unsigned vb = (u & 0x80000000u) ? (u & 0x7fffffffu) : ~u;
                svals[it] = __uint_as_float(vb);
                sidx[it]  = (int)(~(unsigned)(best & 0xffffffffull));
            }
        }
        if (lane == 0) {
            float mx = svals[0], e[TOPK], sum = 0.f;
            #pragma unroll
            for (int i = 0; i < TOPK; i++) { e[i] = expf(svals[i] - mx); sum += e[i]; }
            float inv = 1.f / sum;
            #pragma unroll
            for (int i = 0; i < TOPK; i++) {
                g_w[row * TOPK + i]   = e[i] * inv;
                g_idx[row * TOPK + i] = sidx[i];
                g_used[sidx[i]] = 1;
            }
        }
    }
}

// ---------------- kernel 6: adj_sum over R (used rows only) -----------------
__global__ __launch_bounds__(256) void k_adjsum(const float* __restrict__ adj) {
    int row = blockIdx.x >> 1;
    if (!g_used[row]) return;
    int i = row * (NKEYS / 4) + (blockIdx.x & 1) * 256 + threadIdx.x;
    const float4* a = (const float4*)adj;
    const int stride = NKEYS * NKEYS / 4;
    float4 acc = make_float4(0.f, 0.f, 0.f, 0.f);
    #pragma unroll
    for (int r = 0; r < RDIM; r++) {
        float4 v = a[r * stride + i];
        acc.x += v.x; acc.y += v.y; acc.z += v.z; acc.w += v.w;
    }
    ((float4*)g_adjsum)[i] = acc;
}

// ---------------- kernel 7: nei gather -> hi/lo bf16 planes -----------------
__global__ __launch_bounds__(256) void k_nei() {
    int row = blockIdx.x;
    int tid = threadIdx.x;
    __shared__ float sw[TOPK];
    __shared__ int   si[TOPK];
    if (tid < TOPK) { sw[tid] = g_w[row * TOPK + tid]; si[tid] = g_idx[row * TOPK + tid]; }
    __syncthreads();
    int n0 = blockIdx.y * (NKEYS / 2) + tid * 4;
    float4 a0 = make_float4(0.f, 0.f, 0.f, 0.f);
    #pragma unroll
    for (int kk = 0; kk < TOPK; kk++) {
        float wv = sw[kk];
        float4 v0 = *(const float4*)&g_adjsum[si[kk] * NKEYS + n0];
        a0.x = fmaf(wv, v0.x, a0.x); a0.y = fmaf(wv, v0.y, a0.y);
        a0.z = fmaf(wv, v0.z, a0.z); a0.w = fmaf(wv, v0.w, a0.w);
    }
    uint2 H, L;
    H.x = pack_hi2(a0.x, a0.y); H.y = pack_hi2(a0.z, a0.w);
    L.x = pack_lo2(a0.x, a0.y); L.y = pack_lo2(a0.z, a0.w);
    *(uint2*)&g_neih[row * NKEYS + n0] = H;
    *(uint2*)&g_neil[row * NKEYS + n0] = L;
}

// ---------------- kernel 8: reduce 8 split buffers -> d_out -----------------
__global__ __launch_bounds__(256) void k_reduce(float* __restrict__ out) {
    int i4 = blockIdx.x * 256 + threadIdx.x;       // < 49152 float4s
    const float4* p = (const float4*)g_outp;
    float4 a = make_float4(0.f, 0.f, 0.f, 0.f);
    #pragma unroll
    for (int z = 0; z < 8; z++) {
        float4 v = p[z * (MROWS * DDIM / 4) + i4];
        a.x += v.x; a.y += v.y; a.z += v.z; a.w += v.w;
    }
    ((float4*)out)[i4] = a;
}

// ---------------- launch ----------------------------------------------------
extern "C" void kernel_launch(void* const* d_in, const int* in_sizes, int n_in,
                              void* d_out, int out_size) {
    const float* positions  = (const float*)d_in[0];   // [4,64,768]
    const float* keys_param = (const float*)d_in[1];   // [2048,768]
    const float* adjacency  = (const float*)d_in[2];   // [12,2048,2048]
    float* out = (float*)d_out;                        // [4,64,768]

    __nv_bfloat16 *p_kh, *p_kl, *p_kth, *p_ktl, *p_ph, *p_pl, *p_nh, *p_nl;
    float *p_sc4, *p_outp;
    cudaGetSymbolAddress((void**)&p_kh,   g_keysh);
    cudaGetSymbolAddress((void**)&p_kl,   g_keysl);
    cudaGetSymbolAddress((void**)&p_kth,  g_keysTh);
    cudaGetSymbolAddress((void**)&p_ktl,  g_keysTl);
    cudaGetSymbolAddress((void**)&p_ph,   g_posh);
    cudaGetSymbolAddress((void**)&p_pl,   g_posl);
    cudaGetSymbolAddress((void**)&p_nh,   g_neih);
    cudaGetSymbolAddress((void**)&p_nl,   g_neil);
    cudaGetSymbolAddress((void**)&p_sc4,  g_scores4);
    cudaGetSymbolAddress((void**)&p_outp, g_outp);

    const int GEMM_SMEM = 2 * STAGE_B;      // 131072 bytes
    static int smem_set = 0;
    if (!smem_set) {
        cudaFuncSetAttribute(k_gemm, cudaFuncAttributeMaxDynamicSharedMemorySize,
                             GEMM_SMEM);
        smem_set = 1;
    }

    // 1. normalize keys -> hi/lo; zero used mask
    k_norm<<<NKEYS, 256>>>(keys_param);
    // 2. positions -> hi/lo
    k_prep<<<MROWS * DDIM / 4 / 256, 256>>>(positions);
    // 3. keys transpose (for GEMM2's NT form)
    {
        dim3 grid(DDIM / 32, NKEYS / 32);
        k_transpose<<<grid, dim3(256)>>>();
    }
    // 4. scores = positions @ keys^T  (M=256, N=2048, K=768, split-K=4)
    {
        dim3 grid(NKEYS / 128, MROWS / 128, 4);
        k_gemm<<<grid, 256, GEMM_SMEM>>>(p_ph, p_pl, p_kh, p_kl, p_sc4,
                                         DDIM, DDIM / 4, NKEYS);
    }
    // 5. top-16 + softmax (marks used rows)
    k_topk<<<MROWS, 256>>>();
    // 6. adjacency reduction over R (used rows only)
    k_adjsum<<<NKEYS * 2, 256>>>(adjacency);
    // 7. nei gather -> hi/lo planes
    {
        dim3 grid(MROWS, 2);
        k_nei<<<grid, 256>>>();
    }
    // 8. out = nei @ keys  (M=256, N=768, K=2048, split-K=8)
    {
        dim3 grid(DDIM / 128, MROWS / 128, 8);
        k_gemm<<<grid, 256, GEMM_SMEM>>>(p_nh, p_nl, p_kth, p_ktl, p_outp,
                                         NKEYS, NKEYS / 8, DDIM);
    }
    // 9. reduce split buffers into d_out
    k_reduce<<<MROWS * DDIM / 4 / 256, 256>>>(out);
}